// round 8
// baseline (speedup 1.0000x reference)
#include <cuda_runtime.h>
#include <cuda_fp16.h>
#include <cstdint>

// ---------------------------------------------------------------------------
// FCOS head, fp16 mma.sync (m16n8k16, fp32 accum). Persistent fine-grained
// GEMM: M=128 x N=64 tiles, K-chunk 64, XOR-swizzled 4-slot cp.async ring,
// cross-tile pipelining. Level+path batched.
// ---------------------------------------------------------------------------

#define TP 20267
#define TOTE 10376704
#define NTILES 319
#define SLOT_BYTES 24576       // A 16384 + B 8192
#define DYN_SMEM (4 * SLOT_BYTES)
#define GRIDC 296

__device__ __half g_xh[TOTE];
__device__ __half g_actA[TOTE];
__device__ __half g_actB[TOTE];
__device__ __half g_actC[TOTE];
__device__ __half g_actD[TOTE];
__device__ float  g_y[TOTE];
__device__ float  g_y2[TOTE];
__device__ float  g_mean[640];
__device__ float  g_inv[640];
__device__ float  g_regw[26 * 256 * 9];
__device__ float  g_regb[26];
__device__ __half g_wt_cls[4 * 9 * 256 * 256];   // [s][tap][oc][ic]
__device__ __half g_wt_reg[4 * 9 * 256 * 256];
__device__ __half g_wtc_out[2 * 9 * 128 * 256];  // [part][tap][ocpad][ic]
__device__ __half g_wtr_out[2 * 9 * 128 * 256];

__constant__ int c_Hs[5] = {100, 50, 25, 13, 7};
__constant__ int c_Ws[5] = {152, 76, 38, 19, 10};
__constant__ int c_HWs[5] = {15200, 3800, 950, 247, 70};
__constant__ int c_Ps[5] = {30400, 7600, 1900, 494, 140};
__constant__ int c_tb[5] = {0, 238, 298, 313, 317};
__constant__ int c_ao[5] = {0, 7782400, 9728000, 10214400, 10340864};
__constant__ int c_lb[5] = {0, 15200, 19000, 19950, 20197};

__constant__ long long c_base[26] = {
    3242720LL, 3242720LL, 3242720LL, 3242720LL,
    3404856LL,
    3445390LL, 3445390LL, 3445390LL,
    3566992LL,
    3607526LL, 3607526LL, 3607526LL, 3607526LL, 3607526LL, 3607526LL,
    3607526LL, 3607526LL, 3607526LL, 3607526LL, 3607526LL, 3607526LL,
    3607526LL, 3607526LL, 3607526LL, 3607526LL,
    4256070LL};
__constant__ int c_ctot[26] = {4, 4, 4, 4, 1, 3, 3, 3, 1,
                               16, 16, 16, 16, 16, 16, 16, 16,
                               16, 16, 16, 16, 16, 16, 16, 16, 1};
__constant__ int c_ch[26] = {0, 1, 2, 3, 0, 0, 1, 2, 0,
                             0, 1, 2, 3, 4, 5, 6, 7,
                             8, 9, 10, 11, 12, 13, 14, 15, 0};
__constant__ int c_relu[26] = {1, 1, 1, 1, 0, 0, 0, 0, 0,
                               0, 0, 0, 0, 0, 0, 0, 0,
                               0, 0, 0, 0, 0, 0, 0, 0, 0};

__device__ __forceinline__ void cpa16p(uint32_t d, const void* s, int sz) {
    asm volatile("cp.async.cg.shared.global [%0], [%1], 16, %2;" ::"r"(d), "l"(s), "r"(sz));
}
#define LDSM4(r0, r1, r2, r3, a)                                           \
    asm volatile("ldmatrix.sync.aligned.m8n8.x4.shared.b16 {%0,%1,%2,%3}, [%4];" \
                 : "=r"(r0), "=r"(r1), "=r"(r2), "=r"(r3) : "r"(a))

// ---------------------------------------------------------------------------
__global__ void to_nhwc_half(const float* __restrict__ f0, const float* __restrict__ f1,
                             const float* __restrict__ f2, const float* __restrict__ f3,
                             const float* __restrict__ f4, __half* __restrict__ xh) {
    __shared__ float t[32][33];
    int z = blockIdx.z;
    int lvl = z >> 1, n = z & 1;
    int HW = c_HWs[lvl];
    int p0 = blockIdx.x * 32;
    if (p0 >= HW) return;
    const float* src = lvl == 0 ? f0 : lvl == 1 ? f1 : lvl == 2 ? f2 : lvl == 3 ? f3 : f4;
    __half* dst = xh + c_ao[lvl];
    int c0 = blockIdx.y * 32;
    int tx = threadIdx.x, ty = threadIdx.y;
    int p = p0 + tx;
    if (p < HW) t[ty][tx] = src[((size_t)(n * 256 + c0 + ty)) * HW + p];
    __syncthreads();
    int p2 = p0 + ty, c2 = c0 + tx;
    if (p2 < HW) dst[((size_t)(n * HW + p2)) * 256 + c2] = __float2half_rn(t[tx][ty]);
}

__global__ void pack_wt(const float* __restrict__ w, __half* __restrict__ wt) {
    int idx = blockIdx.x * blockDim.x + threadIdx.x;
    if (idx >= 4 * 9 * 256 * 256) return;
    int ic = idx & 255;
    int oc = (idx >> 8) & 255;
    int tap = (idx >> 16) % 9;
    int s = idx / 589824;
    wt[idx] = __float2half_rn(w[(((size_t)(s * 256 + oc) * 256 + ic) * 9) + tap]);
}

__global__ void pack_headw(const float* __restrict__ src, __half* __restrict__ dst,
                           int OC) {
    int idx = blockIdx.x * blockDim.x + threadIdx.x;
    if (idx >= 2 * 9 * 128 * 256) return;
    int ic = idx & 255;
    int oc = (idx >> 8) & 127;
    int tap = (idx >> 15) % 9;
    int part = idx / (9 * 128 * 256);
    float v = 0.f;
    if (oc < OC) v = src[((size_t)oc * 256 + ic) * 9 + tap];
    __half hi = __float2half_rn(v);
    dst[idx] = (part == 0) ? hi : __float2half_rn(v - __half2float(hi));
}

__global__ void pack_reg(const float* __restrict__ bbox_w, const float* __restrict__ bbox_b,
                         const float* __restrict__ ctr_w,  const float* __restrict__ ctr_b,
                         const float* __restrict__ dim_w,  const float* __restrict__ dim_b,
                         const float* __restrict__ ori_w,  const float* __restrict__ ori_b,
                         const float* __restrict__ kp_w,   const float* __restrict__ kp_b,
                         const float* __restrict__ depth_w,const float* __restrict__ depth_b) {
    int idx = blockIdx.x * blockDim.x + threadIdx.x;
    int total = 26 * 2304;
    if (idx < total) {
        int oc = idx / 2304;
        int r = idx % 2304;
        const float* src;
        if (oc < 4)       src = bbox_w + oc * 2304;
        else if (oc == 4) src = ctr_w;
        else if (oc < 8)  src = dim_w + (oc - 5) * 2304;
        else if (oc == 8) src = ori_w;
        else if (oc < 25) src = kp_w + (oc - 9) * 2304;
        else              src = depth_w;
        g_regw[idx] = src[r];
    }
    if (idx < 26) {
        float b;
        if (idx < 4)       b = bbox_b[idx];
        else if (idx == 4) b = ctr_b[0];
        else if (idx < 8)  b = dim_b[idx - 5];
        else if (idx == 8) b = ori_b[0];
        else if (idx < 25) b = kp_b[idx - 9];
        else               b = depth_b[0];
        g_regb[idx] = b;
    }
}

// ---------------------------------------------------------------------------
// Persistent GEMM. kind 0: towers (work = 319*8: col = path*4 + oc quarter).
// kind 1: heads  (work = 319*3: col 0,1 = cls oc0 0/64; col 2 = reg).
// ---------------------------------------------------------------------------
struct Ctx {
    const __half* x;
    int H, W, HW, P, p0, oc0, path, lvl;
};

__global__ __launch_bounds__(256, 2) void gemm16p(
    const __half* __restrict__ x0, const __half* __restrict__ x1,
    const __half* __restrict__ wt0, const __half* __restrict__ wt1,
    const float* __restrict__ b0p, const float* __restrict__ b1p,
    float* __restrict__ out0, float* __restrict__ out1, int kind) {
    extern __shared__ __align__(16) uint32_t dynsm[];
    __shared__ int syy[2][128], sxx[2][128], sn[2][128];

    const int NST = kind ? 72 : 36;
    const int NCOL = kind ? 3 : 8;
    const int TOTW = NTILES * NCOL;
    int tid = threadIdx.x;
    int G = gridDim.x;
    int widx0 = blockIdx.x;
    int NTloc = (TOTW - widx0 + G - 1) / G;
    int TOTS = NTloc * NST;

    uint32_t smbase = (uint32_t)__cvta_generic_to_shared(dynsm);
    int warp = tid >> 5, lane = tid & 31, g = lane >> 2, t4 = lane & 3;
    int mwarp = (warp >> 1) * 32, nwarp = (warp & 1) * 32;
    int rxA0 = mwarp + (lane & 15);
    int hiA = lane >> 4;
    int rB0 = nwarp + ((lane >> 4) << 3) + (lane & 7);
    int hiB = (lane >> 3) & 1;
    int am = tid >> 3, ach = tid & 7;

    auto make_ctx = [&](int widx, Ctx& c) {
        int col = widx / NTILES;
        int bx = widx - col * NTILES;
        int lvl = (bx >= c_tb[1]) + (bx >= c_tb[2]) + (bx >= c_tb[3]) + (bx >= c_tb[4]);
        c.lvl = lvl; c.H = c_Hs[lvl]; c.W = c_Ws[lvl];
        c.HW = c_HWs[lvl]; c.P = c_Ps[lvl];
        c.p0 = (bx - c_tb[lvl]) * 128;
        if (kind == 0) { c.path = col >> 2; c.oc0 = (col & 3) * 64; }
        else           { c.path = (col == 2) ? 1 : 0; c.oc0 = (col == 1) ? 64 : 0; }
        c.x = (c.path ? x1 : x0) + c_ao[lvl];
    };
    auto fill_tables = [&](const Ctx& c, int b) {
        if (tid < 128) {
            int p = c.p0 + tid;
            if (p < c.P) {
                int n = p >= c.HW ? 1 : 0;
                int rr = p - n * c.HW;
                int yy = rr / c.W;
                syy[b][tid] = yy; sxx[b][tid] = rr - yy * c.W; sn[b][tid] = n;
            } else {
                syy[b][tid] = -100000; sxx[b][tid] = -100000; sn[b][tid] = 0;
            }
        }
    };
    auto load_chunk = [&](const Ctx& c, int b, int cc, int slot) {
        uint32_t base = smbase + slot * SLOT_BYTES;
        int part = 0;
        if (kind) { part = cc >= 36 ? 1 : 0; cc -= part * 36; }
        int tap = cc >> 2, icc = (cc & 3) << 6;
        int tq = tap / 3;
        int dy = tq - 1, dx = tap - tq * 3 - 1;
#pragma unroll
        for (int j = 0; j < 4; j++) {
            int m = am + j * 32;
            int gy = syy[b][m] + dy, gx = sxx[b][m] + dx;
            bool v = ((unsigned)gy < (unsigned)c.H) && ((unsigned)gx < (unsigned)c.W);
            const __half* src =
                c.x + ((size_t)(sn[b][m] * c.HW + gy * c.W + gx) * 256 + icc + ach * 8);
            cpa16p(base + m * 128 + ((ach ^ (m & 7)) << 4),
                   v ? src : (const __half*)c.x, v ? 16 : 0);
        }
        const __half* wt = c.path ? wt1 : wt0;
        const __half* wbase =
            kind ? wt + ((size_t)((part * 9 + tap) * 128 + c.oc0)) * 256
                 : wt + ((size_t)(tap * 256 + c.oc0)) * 256;
#pragma unroll
        for (int j = 0; j < 2; j++) {
            int r = am + j * 32;
            cpa16p(base + 16384 + r * 128 + ((ach ^ (r & 7)) << 4),
                   wbase + (size_t)r * 256 + icc + ach * 8, 16);
        }
        asm volatile("cp.async.commit_group;");
    };

    Ctx cur, nxt;
    make_ctx(widx0, cur);
    fill_tables(cur, 0);
    if (NTloc > 1) { make_ctx(widx0 + G, nxt); fill_tables(nxt, 1); }
    __syncthreads();

    load_chunk(cur, 0, 0, 0);
    load_chunk(cur, 0, 1, 1);
    load_chunk(cur, 0, 2, 2);

    int gs = 0;
    for (int k = 0; k < NTloc; k++) {
        if (k > 0) {
            __syncthreads();
            cur = nxt;
            if (k + 1 < NTloc) {
                make_ctx(widx0 + (k + 1) * G, nxt);
                fill_tables(nxt, (k + 1) & 1);
            }
            __syncthreads();
        }

        float acc[2][4][4];
#pragma unroll
        for (int i = 0; i < 2; i++)
#pragma unroll
            for (int j = 0; j < 4; j++)
#pragma unroll
                for (int q = 0; q < 4; q++) acc[i][j][q] = 0.f;

        int kNST = (k + 1) * NST;
        for (int s = 0; s < NST; s++, gs++) {
            int pend = TOTS - gs - 1;
            if (pend >= 2) asm volatile("cp.async.wait_group 2;" ::: "memory");
            else if (pend == 1) asm volatile("cp.async.wait_group 1;" ::: "memory");
            else asm volatile("cp.async.wait_group 0;" ::: "memory");
            __syncthreads();
            int g2 = gs + 3;
            if (g2 < TOTS) {
                if (g2 < kNST) load_chunk(cur, k & 1, g2 - k * NST, g2 & 3);
                else           load_chunk(nxt, (k + 1) & 1, g2 - kNST, g2 & 3);
            }

            uint32_t sb = smbase + (gs & 3) * SLOT_BYTES;
#pragma unroll
            for (int kb = 0; kb < 4; kb++) {
                int ch = kb * 2;
                uint32_t A[2][4], Bv[2][4];
#pragma unroll
                for (int mt = 0; mt < 2; mt++) {
                    int row = rxA0 + mt * 16;
                    LDSM4(A[mt][0], A[mt][1], A[mt][2], A[mt][3],
                          sb + row * 128 + (((ch + hiA) ^ (row & 7)) << 4));
                }
#pragma unroll
                for (int ntp = 0; ntp < 2; ntp++) {
                    int row = rB0 + ntp * 16;
                    LDSM4(Bv[ntp][0], Bv[ntp][1], Bv[ntp][2], Bv[ntp][3],
                          sb + 16384 + row * 128 + (((ch + hiB) ^ (row & 7)) << 4));
                }
#pragma unroll
                for (int mt = 0; mt < 2; mt++)
#pragma unroll
                    for (int nt = 0; nt < 4; nt++) {
                        int ntp = nt >> 1, j = nt & 1;
                        asm volatile(
                            "mma.sync.aligned.m16n8k16.row.col.f32.f16.f16.f32 "
                            "{%0,%1,%2,%3}, {%4,%5,%6,%7}, {%8,%9}, {%0,%1,%2,%3};"
                            : "+f"(acc[mt][nt][0]), "+f"(acc[mt][nt][1]),
                              "+f"(acc[mt][nt][2]), "+f"(acc[mt][nt][3])
                            : "r"(A[mt][0]), "r"(A[mt][1]), "r"(A[mt][2]), "r"(A[mt][3]),
                              "r"(Bv[ntp][j * 2]), "r"(Bv[ntp][j * 2 + 1]));
                    }
            }
        }

        // epilogue for tile k (tables buf k&1)
        int tb = k & 1;
        const float* bias = cur.path ? b1p : b0p;
        float* outp = cur.path ? out1 : out0;
        int OC = kind ? (cur.path ? 26 : 80) : 256;
#pragma unroll
        for (int nt = 0; nt < 4; nt++) {
            int oc = cur.oc0 + nwarp + nt * 8 + 2 * t4;
#pragma unroll
            for (int mt = 0; mt < 2; mt++) {
#pragma unroll
                for (int hf = 0; hf < 2; hf++) {
                    int r = mwarp + mt * 16 + g + hf * 8;
                    if (cur.p0 + r >= cur.P) continue;
                    float v0 = acc[mt][nt][hf * 2];
                    float v1 = acc[mt][nt][hf * 2 + 1];
                    if (kind == 0) {
                        size_t ob = (size_t)c_ao[cur.lvl] +
                                    (size_t)(cur.p0 + r) * 256 + oc;
                        float2 st = {v0 + __ldg(&bias[oc]), v1 + __ldg(&bias[oc + 1])};
                        *(float2*)&outp[ob] = st;
                    } else if (oc < OC) {
                        long long unit = (long long)sn[tb][r] * TP + c_lb[cur.lvl] +
                                         syy[tb][r] * cur.W + sxx[tb][r];
                        v0 += __ldg(&bias[oc]);
                        bool two = (oc + 1) < OC;
                        if (two) v1 += __ldg(&bias[oc + 1]);
                        if (cur.path == 0) {
                            outp[unit * 80 + oc] = v0;
                            if (two) outp[unit * 80 + oc + 1] = v1;
                        } else {
                            if (c_relu[oc]) v0 = fmaxf(v0, 0.f);
                            outp[c_base[oc] + unit * c_ctot[oc] + c_ch[oc]] = v0;
                            if (two) {
                                if (c_relu[oc + 1]) v1 = fmaxf(v1, 0.f);
                                outp[c_base[oc + 1] + unit * c_ctot[oc + 1] +
                                     c_ch[oc + 1]] = v1;
                            }
                        }
                    }
                }
            }
        }
    }
}

// ---------------------------------------------------------------------------
// GroupNorm (both paths per launch)
// ---------------------------------------------------------------------------
__global__ void gn_reduce(const float* __restrict__ y0, const float* __restrict__ y1) {
    int bid = blockIdx.x;
    int pathv = bid >= 320 ? 1 : 0;
    int b2 = bid - pathv * 320;
    int l = b2 >> 6;
    int ng = b2 & 63;
    int n = ng >> 5, gr = ng & 31;
    int HW = c_HWs[l];
    const float* y = pathv ? y1 : y0;
    const float* base =
        y + c_ao[l] + (size_t)n * HW * 256 + gr * 8 + (threadIdx.x & 1) * 4;
    int tid = threadIdx.x;
    float s = 0.f, sq = 0.f;
    for (int p = tid >> 1; p < HW; p += 128) {
        float4 v = *(const float4*)&base[(size_t)p * 256];
        s += v.x + v.y + v.z + v.w;
        sq += v.x * v.x + v.y * v.y + v.z * v.z + v.w * v.w;
    }
    __shared__ float ss[256], ssq[256];
    ss[tid] = s; ssq[tid] = sq;
    __syncthreads();
    for (int off = 128; off > 0; off >>= 1) {
        if (tid < off) { ss[tid] += ss[tid + off]; ssq[tid] += ssq[tid + off]; }
        __syncthreads();
    }
    if (tid == 0) {
        float M = 8.f * HW;
        float mu = ss[0] / M;
        float var = ssq[0] / M - mu * mu;
        g_mean[bid] = mu;
        g_inv[bid] = rsqrtf(var + 1e-5f);
    }
}

__global__ void gn_apply(const float* __restrict__ y0, const float* __restrict__ y1,
                         __half* __restrict__ d0, __half* __restrict__ d1,
                         const float* __restrict__ gm0, const float* __restrict__ gm1,
                         const float* __restrict__ bt0, const float* __restrict__ bt1) {
    int idx = blockIdx.x * blockDim.x + threadIdx.x;
    if (idx >= TOTE / 4) return;
    int pathv = blockIdx.y;
    const float* y = pathv ? y1 : y0;
    __half* act = pathv ? d1 : d0;
    const float* gamma = pathv ? gm1 : gm0;
    const float* beta = pathv ? bt1 : bt0;
    int e = idx * 4;
    int l = (e >= c_ao[1]) + (e >= c_ao[2]) + (e >= c_ao[3]) + (e >= c_ao[4]);
    int c = e & 255;
    int pl = (e - c_ao[l]) >> 8;
    int n = pl >= c_HWs[l] ? 1 : 0;
    int ng = pathv * 320 + l * 64 + n * 32 + (c >> 3);
    float mu = g_mean[ng], iv = g_inv[ng];
    float4 v = *(const float4*)&y[e];
    float4 gmv = *(const float4*)&gamma[c];
    float4 btv = *(const float4*)&beta[c];
    __half2 h0 = __floats2half2_rn(fmaxf((v.x - mu) * iv * gmv.x + btv.x, 0.f),
                                   fmaxf((v.y - mu) * iv * gmv.y + btv.y, 0.f));
    __half2 h1 = __floats2half2_rn(fmaxf((v.z - mu) * iv * gmv.z + btv.z, 0.f),
                                   fmaxf((v.w - mu) * iv * gmv.w + btv.w, 0.f));
    uint2 st = {*(uint32_t*)&h0, *(uint32_t*)&h1};
    *(uint2*)&act[e] = st;
}

// ---------------------------------------------------------------------------
extern "C" void kernel_launch(void* const* d_in, const int* in_sizes, int n_in,
                              void* d_out, int out_size) {
    const float* feats[5];
    for (int i = 0; i < 5; i++) feats[i] = (const float*)d_in[i];
    const float* cls_conv_w = (const float*)d_in[5];
    const float* cls_conv_b = (const float*)d_in[6];
    const float* cls_gn_w = (const float*)d_in[7];
    const float* cls_gn_b = (const float*)d_in[8];
    const float* cls_out_w = (const float*)d_in[9];
    const float* cls_out_b = (const float*)d_in[10];
    const float* reg_conv_w = (const float*)d_in[11];
    const float* reg_conv_b = (const float*)d_in[12];
    const float* reg_gn_w = (const float*)d_in[13];
    const float* reg_gn_b = (const float*)d_in[14];
    float* out = (float*)d_out;

    __half *xh, *actA, *actB, *actC, *actD, *wtc, *wtr, *wtco, *wtro;
    float *ybuf, *ybuf2, *regw, *regb;
    cudaGetSymbolAddress((void**)&xh, g_xh);
    cudaGetSymbolAddress((void**)&actA, g_actA);
    cudaGetSymbolAddress((void**)&actB, g_actB);
    cudaGetSymbolAddress((void**)&actC, g_actC);
    cudaGetSymbolAddress((void**)&actD, g_actD);
    cudaGetSymbolAddress((void**)&ybuf, g_y);
    cudaGetSymbolAddress((void**)&ybuf2, g_y2);
    cudaGetSymbolAddress((void**)&regw, g_regw);
    cudaGetSymbolAddress((void**)&regb, g_regb);
    cudaGetSymbolAddress((void**)&wtc, g_wt_cls);
    cudaGetSymbolAddress((void**)&wtr, g_wt_reg);
    cudaGetSymbolAddress((void**)&wtco, g_wtc_out);
    cudaGetSymbolAddress((void**)&wtro, g_wtr_out);

    cudaFuncSetAttribute(gemm16p, cudaFuncAttributeMaxDynamicSharedMemorySize,
                         DYN_SMEM);

    pack_reg<<<(26 * 2304 + 255) / 256, 256>>>(
        (const float*)d_in[15], (const float*)d_in[16],
        (const float*)d_in[17], (const float*)d_in[18],
        (const float*)d_in[19], (const float*)d_in[20],
        (const float*)d_in[21], (const float*)d_in[22],
        (const float*)d_in[23], (const float*)d_in[24],
        (const float*)d_in[25], (const float*)d_in[26]);

    int wtN = 4 * 9 * 256 * 256;
    pack_wt<<<(wtN + 255) / 256, 256>>>(cls_conv_w, wtc);
    pack_wt<<<(wtN + 255) / 256, 256>>>(reg_conv_w, wtr);
    int hN = 2 * 9 * 128 * 256;
    pack_headw<<<(hN + 255) / 256, 256>>>(cls_out_w, wtco, 80);
    pack_headw<<<(hN + 255) / 256, 256>>>(regw, wtro, 26);

    to_nhwc_half<<<dim3(475, 8, 10), dim3(32, 32)>>>(feats[0], feats[1], feats[2],
                                                     feats[3], feats[4], xh);

    int gApplyX = (TOTE / 4 + 255) / 256;
    const __half* curc = xh;
    const __half* curr = xh;
    __half* cd[4] = {actA, actB, actA, actB};
    __half* rd[4] = {actC, actD, actC, actD};
    for (int s = 0; s < 4; s++) {
        gemm16p<<<GRIDC, 256, DYN_SMEM>>>(
            curc, curr, wtc + (size_t)s * 589824, wtr + (size_t)s * 589824,
            cls_conv_b + s * 256, reg_conv_b + s * 256, ybuf, ybuf2, 0);
        gn_reduce<<<640, 256>>>(ybuf, ybuf2);
        gn_apply<<<dim3(gApplyX, 2), 256>>>(ybuf, ybuf2, cd[s], rd[s],
                                            cls_gn_w + s * 256, reg_gn_w + s * 256,
                                            cls_gn_b + s * 256, reg_gn_b + s * 256);
        curc = cd[s];
        curr = rd[s];
    }
    // heads: col 0,1 = cls (reads actB), col 2 = reg (reads actD)
    gemm16p<<<GRIDC, 256, DYN_SMEM>>>(actB, actD, wtco, wtro, cls_out_b, regb,
                                      out, out, 1);
    (void)in_sizes; (void)n_in; (void)out_size;
}